// round 1
// baseline (speedup 1.0000x reference)
#include <cuda_runtime.h>
#include <cstdint>

#define HWSZ 268324
#define HT 518
#define WD 518
#define NIMG 64
#define BINS 2048
#define SHIFT 21
#define LOWMASK 0x1FFFFFu
#define CAP 32768
#define BPI 8
#define EPSV 1e-8

// ---------------- scratch (static __device__, no allocations) ----------------
__device__ unsigned g_hist[128][BINS];     // per (img,tensor) histogram
__device__ double   g_bsum[128][BINS];     // per-bucket value sums
__device__ unsigned g_cnt[NIMG];           // valid-pixel counts
__device__ unsigned g_bucket[128];
__device__ unsigned g_kp[128];             // rank within bucket
__device__ unsigned g_belowC[128];
__device__ double   g_belowS[128];
__device__ double   g_stot[128];
__device__ unsigned g_ccnt[128];
__device__ float    g_cand[128][CAP];
__device__ float    g_med[128];
__device__ float    g_isc[128];            // 1/sc
__device__ double   g_rho[NIMG];
__device__ double   g_gx[4], g_gy[4];
__device__ unsigned long long g_cx[4], g_cy[4];
__device__ int      g_mmode;

__device__ float         d1buf[NIMG * 259 * 259];
__device__ unsigned char m1buf[NIMG * 259 * 259];
__device__ float         d2buf[NIMG * 129 * 129];
__device__ unsigned char m2buf[NIMG * 129 * 129];
__device__ float         d3buf[NIMG * 64 * 64];
__device__ unsigned char m3buf[NIMG * 64 * 64];

// ---------------- helpers ----------------
__device__ __forceinline__ unsigned monot(float x) {
    unsigned u = __float_as_uint(x);
    return (u >> 31) ? ~u : (u | 0x80000000u);
}
__device__ __forceinline__ float inv_monot(unsigned k) {
    unsigned u = (k >> 31) ? (k & 0x7FFFFFFFu) : ~k;
    return __uint_as_float(u);
}
__device__ __forceinline__ bool mask_at(const void* m, int i, int mode) {
    if (mode == 0) return ((const unsigned char*)m)[i] != 0;
    if (mode == 2) return ((const int*)m)[i] != 0;
    return ((const float*)m)[i] != 0.f;
}

__device__ __forceinline__ double blockReduceD(double v, double* sh) {
    for (int o = 16; o; o >>= 1) v += __shfl_down_sync(0xffffffffu, v, o);
    int w = threadIdx.x >> 5, l = threadIdx.x & 31;
    if (l == 0) sh[w] = v;
    __syncthreads();
    double r = 0;
    if (threadIdx.x < 8) {
        r = sh[threadIdx.x];
        for (int o = 4; o; o >>= 1) r += __shfl_down_sync(0xffu, r, o);
    }
    return r;
}
__device__ __forceinline__ unsigned long long blockReduceU(unsigned long long v, unsigned long long* sh) {
    for (int o = 16; o; o >>= 1) v += __shfl_down_sync(0xffffffffu, v, o);
    int w = threadIdx.x >> 5, l = threadIdx.x & 31;
    if (l == 0) sh[w] = v;
    __syncthreads();
    unsigned long long r = 0;
    if (threadIdx.x < 8) {
        r = sh[threadIdx.x];
        for (int o = 4; o; o >>= 1) r += __shfl_down_sync(0xffu, r, o);
    }
    return r;
}

// ---------------- kernels ----------------
__global__ void k_init(const void* mask) {
    int tid = blockIdx.x * blockDim.x + threadIdx.x;
    int T = gridDim.x * blockDim.x;
    unsigned* h = &g_hist[0][0];
    for (int i = tid; i < 128 * BINS; i += T) h[i] = 0u;
    double* bs = &g_bsum[0][0];
    for (int i = tid; i < 128 * BINS; i += T) bs[i] = 0.0;
    for (int i = tid; i < NIMG; i += T) { g_cnt[i] = 0u; g_rho[i] = 0.0; }
    for (int i = tid; i < 128; i += T) g_ccnt[i] = 0u;
    if (tid < 4) { g_gx[tid] = 0.0; g_gy[tid] = 0.0; g_cx[tid] = 0ull; g_cy[tid] = 0ull; }
    if (tid == 0) {
        // Sniff mask dtype from first 256 bytes (deterministic per input).
        const unsigned char* b = (const unsigned char*)mask;
        bool nonbin = false, offnz = false;
        for (int j = 0; j < 256; j++) {
            unsigned char v = b[j];
            if (v > 1) nonbin = true;
            if ((j & 3) && v) offnz = true;
        }
        g_mmode = nonbin ? 1 : (offnz ? 0 : 2);  // 1=float32, 0=bool/u8, 2=int32
    }
}

__global__ void __launch_bounds__(256) k_hist(const float* __restrict__ pred,
                                              const float* __restrict__ yv,
                                              const void* __restrict__ mask) {
    __shared__ unsigned hc[2][BINS];
    __shared__ float hs[2][BINS];
    __shared__ unsigned blkCnt;
    int tid = threadIdx.x;
    for (int i = tid; i < BINS; i += 256) { hc[0][i] = 0u; hc[1][i] = 0u; hs[0][i] = 0.f; hs[1][i] = 0.f; }
    if (tid == 0) blkCnt = 0u;
    __syncthreads();
    int img = blockIdx.y;
    int per = (HWSZ + BPI - 1) / BPI;
    int s = blockIdx.x * per, e = min(s + per, HWSZ);
    int base = img * HWSZ;
    int mode = g_mmode;
    unsigned mc = 0;
    for (int i = s + tid; i < e; i += 256) {
        if (mask_at(mask, base + i, mode)) {
            mc++;
            float p = pred[base + i];
            unsigned kp = monot(p) >> SHIFT;
            atomicAdd(&hc[0][kp], 1u); atomicAdd(&hs[0][kp], p);
            float q = yv[base + i];
            unsigned kq = monot(q) >> SHIFT;
            atomicAdd(&hc[1][kq], 1u); atomicAdd(&hs[1][kq], q);
        }
    }
    atomicAdd(&blkCnt, mc);
    __syncthreads();
    for (int i = tid; i < BINS; i += 256) {
        unsigned c0 = hc[0][i];
        if (c0) { atomicAdd(&g_hist[2 * img][i], c0); atomicAdd(&g_bsum[2 * img][i], (double)hs[0][i]); }
        unsigned c1 = hc[1][i];
        if (c1) { atomicAdd(&g_hist[2 * img + 1][i], c1); atomicAdd(&g_bsum[2 * img + 1][i], (double)hs[1][i]); }
    }
    if (tid == 0) atomicAdd(&g_cnt[img], blkCnt);
}

__global__ void k_findbucket() {
    int t = blockIdx.x, img = t >> 1, tid = threadIdx.x;
    __shared__ unsigned pc[256];
    __shared__ double ps[256];
    const int CH = BINS / 256;  // 8
    unsigned c = 0; double s = 0;
    for (int j = 0; j < CH; j++) { c += g_hist[t][tid * CH + j]; s += g_bsum[t][tid * CH + j]; }
    pc[tid] = c; ps[tid] = s;
    __syncthreads();
    if (tid == 0) {
        double tot = 0;
        for (int j = 0; j < 256; j++) tot += ps[j];
        g_stot[t] = tot;
        unsigned cnt = g_cnt[img];
        if (cnt == 0) { g_bucket[t] = 0xFFFFFFFFu; g_med[t] = 0.f; g_isc[t] = (float)(1.0 / EPSV); return; }
        unsigned idx = (cnt - 1) >> 1;
        unsigned cum = 0; double cums = 0; int ch = 0;
        while (cum + pc[ch] <= idx) { cum += pc[ch]; cums += ps[ch]; ch++; }
        int b = ch * CH;
        while (cum + g_hist[t][b] <= idx) { cum += g_hist[t][b]; cums += g_bsum[t][b]; b++; }
        g_bucket[t] = (unsigned)b; g_kp[t] = idx - cum; g_belowC[t] = cum; g_belowS[t] = cums;
    }
}

__global__ void __launch_bounds__(256) k_collect(const float* __restrict__ pred,
                                                 const float* __restrict__ yv,
                                                 const void* __restrict__ mask) {
    int img = blockIdx.y, tid = threadIdx.x;
    unsigned bp = g_bucket[2 * img], bq = g_bucket[2 * img + 1];
    int per = (HWSZ + BPI - 1) / BPI;
    int s = blockIdx.x * per, e = min(s + per, HWSZ);
    int base = img * HWSZ;
    int mode = g_mmode;
    for (int i = s + tid; i < e; i += 256) {
        if (!mask_at(mask, base + i, mode)) continue;
        float p = pred[base + i];
        if ((monot(p) >> SHIFT) == bp) {
            unsigned pos = atomicAdd(&g_ccnt[2 * img], 1u);
            if (pos < CAP) g_cand[2 * img][pos] = p;
        }
        float q = yv[base + i];
        if ((monot(q) >> SHIFT) == bq) {
            unsigned pos = atomicAdd(&g_ccnt[2 * img + 1], 1u);
            if (pos < CAP) g_cand[2 * img + 1][pos] = q;
        }
    }
}

__global__ void k_select() {
    int t = blockIdx.x, img = t >> 1, tid = threadIdx.x;
    unsigned cnt = g_cnt[img];
    if (cnt == 0) return;  // med/isc already set
    int n = (int)min(g_ccnt[t], (unsigned)CAP);
    unsigned kp = g_kp[t];
    __shared__ unsigned cS;
    unsigned prefix = 0;
    for (int b = SHIFT - 1; b >= 0; b--) {
        if (tid == 0) cS = 0u;
        __syncthreads();
        unsigned hiMask = (LOWMASK >> (b + 1)) << (b + 1);
        unsigned loc = 0;
        for (int i = tid; i < n; i += blockDim.x) {
            unsigned key = monot(g_cand[t][i]) & LOWMASK;
            if ((key & hiMask) == prefix && ((key >> b) & 1u) == 0u) loc++;
        }
        atomicAdd(&cS, loc);
        __syncthreads();
        unsigned c = cS;
        if (kp < c) { /* bit stays 0 */ } else { kp -= c; prefix |= (1u << b); }
        __syncthreads();
    }
    unsigned mkey = (g_bucket[t] << SHIFT) | prefix;
    float med = inv_monot(mkey);
    __shared__ unsigned nltS;
    __shared__ double sltS;
    if (tid == 0) { nltS = 0u; sltS = 0.0; }
    __syncthreads();
    unsigned nl = 0; double sl = 0;
    for (int i = tid; i < n; i += blockDim.x) {
        float v = g_cand[t][i];
        if (monot(v) < mkey) { nl++; sl += (double)v; }
    }
    atomicAdd(&nltS, nl); atomicAdd(&sltS, sl);
    __syncthreads();
    if (tid == 0) {
        double nb = (double)(g_belowC[t] + nltS);
        double Sb = g_belowS[t] + sltS;
        double abs_sum = g_stot[t] - 2.0 * Sb + (double)med * (2.0 * nb - (double)cnt);
        double sc = abs_sum / (double)cnt + EPSV;
        g_med[t] = med;
        g_isc[t] = (float)(1.0 / sc);
    }
}

// Fused: diff, loss_ssi, level-0 gradients, 2x-pool to level 1.
__global__ void __launch_bounds__(256) k_main(const float* __restrict__ pred,
                                              const float* __restrict__ yv,
                                              const void* __restrict__ mask) {
    __shared__ float sd[15][520];
    __shared__ unsigned char smk[15][520];
    __shared__ double redD[8];
    __shared__ unsigned long long redU[8];
    int img = blockIdx.y, band = blockIdx.x, tid = threadIdx.x;
    int r0 = band * 14;
    int nrows = (band < 36) ? 15 : 14;  // +1 halo row except last band
    float medp = g_med[2 * img], medy = g_med[2 * img + 1];
    float iscp = g_isc[2 * img], iscy = g_isc[2 * img + 1];
    int base = img * HWSZ + r0 * WD;
    int mode = g_mmode;
    for (int i = tid; i < nrows * WD; i += 256) {
        int rr = i / WD, c = i - rr * WD;
        int gi = base + i;
        bool m = mask_at(mask, gi, mode);
        float d = (pred[gi] - medp) * iscp - (yv[gi] - medy) * iscy;
        sd[rr][c] = d;
        smk[rr][c] = m ? 1 : 0;
    }
    __syncthreads();
    double rho = 0.0, gx = 0.0, gy = 0.0;
    unsigned cx = 0, cy = 0;
    for (int i = tid; i < 14 * WD; i += 256) {
        int rr = i / WD, c = i - rr * WD;
        unsigned char m = smk[rr][c];
        float d = sd[rr][c];
        if (m) rho += (double)fabsf(d);
        if (c < WD - 1 && m && smk[rr][c + 1]) { gx += (double)fabsf(sd[rr][c + 1] - d); cx++; }
    }
    int np = (band < 36) ? 14 : 13;  // vertical pairs starting in this band
    for (int i = tid; i < np * WD; i += 256) {
        int rr = i / WD, c = i - rr * WD;
        if (smk[rr][c] && smk[rr + 1][c]) { gy += (double)fabsf(sd[rr + 1][c] - sd[rr][c]); cy++; }
    }
    // 2x2 pooling -> level 1 (band contributes 7 pooled rows of width 259)
    for (int i = tid; i < 7 * 259; i += 256) {
        int pr = i / 259, pcn = i - pr * 259;
        int rr = 2 * pr, c = 2 * pcn;
        float v = 0.25f * (sd[rr][c] + sd[rr][c + 1] + sd[rr + 1][c] + sd[rr + 1][c + 1]);
        unsigned char any = smk[rr][c] | smk[rr][c + 1] | smk[rr + 1][c] | smk[rr + 1][c + 1];
        int o = img * (259 * 259) + (band * 7 + pr) * 259 + pcn;
        d1buf[o] = v;
        m1buf[o] = any;
    }
    double r1 = blockReduceD(rho, redD); __syncthreads();
    double r2 = blockReduceD(gx, redD);  __syncthreads();
    double r3 = blockReduceD(gy, redD);  __syncthreads();
    unsigned long long u1 = blockReduceU((unsigned long long)cx, redU); __syncthreads();
    unsigned long long u2 = blockReduceU((unsigned long long)cy, redU);
    if (tid == 0) {
        atomicAdd(&g_rho[img], r1);
        atomicAdd(&g_gx[0], r2); atomicAdd(&g_gy[0], r3);
        atomicAdd(&g_cx[0], u1); atomicAdd(&g_cy[0], u2);
    }
}

__global__ void __launch_bounds__(256) k_grad(int lvl) {
    const float* d; const unsigned char* m; int Hc, Wc;
    if (lvl == 1) { d = d1buf; m = m1buf; Hc = 259; Wc = 259; }
    else if (lvl == 2) { d = d2buf; m = m2buf; Hc = 129; Wc = 129; }
    else { d = d3buf; m = m3buf; Hc = 64; Wc = 64; }
    __shared__ double redD[8];
    __shared__ unsigned long long redU[8];
    int per = Hc * Wc, total = NIMG * per;
    double gx = 0, gy = 0;
    unsigned cx = 0, cy = 0;
    for (int i = blockIdx.x * blockDim.x + threadIdx.x; i < total; i += gridDim.x * blockDim.x) {
        if (!m[i]) continue;
        int rem = i % per;
        int r = rem / Wc, c = rem - r * Wc;
        float dv = d[i];
        if (c < Wc - 1 && m[i + 1]) { gx += (double)fabsf(d[i + 1] - dv); cx++; }
        if (r < Hc - 1 && m[i + Wc]) { gy += (double)fabsf(d[i + Wc] - dv); cy++; }
    }
    double r2 = blockReduceD(gx, redD); __syncthreads();
    double r3 = blockReduceD(gy, redD); __syncthreads();
    unsigned long long u1 = blockReduceU((unsigned long long)cx, redU); __syncthreads();
    unsigned long long u2 = blockReduceU((unsigned long long)cy, redU);
    if (threadIdx.x == 0) {
        atomicAdd(&g_gx[lvl], r2); atomicAdd(&g_gy[lvl], r3);
        atomicAdd(&g_cx[lvl], u1); atomicAdd(&g_cy[lvl], u2);
    }
}

__global__ void __launch_bounds__(256) k_pool(int lvl) {
    const float* din; const unsigned char* mi; float* dout; unsigned char* mo;
    int Hi, Wi, Ho, Wo;
    if (lvl == 1) { din = d1buf; mi = m1buf; dout = d2buf; mo = m2buf; Hi = 259; Wi = 259; Ho = 129; Wo = 129; }
    else { din = d2buf; mi = m2buf; dout = d3buf; mo = m3buf; Hi = 129; Wi = 129; Ho = 64; Wo = 64; }
    int per = Ho * Wo, total = NIMG * per;
    for (int i = blockIdx.x * blockDim.x + threadIdx.x; i < total; i += gridDim.x * blockDim.x) {
        int img = i / per, rem = i - img * per;
        int r = rem / Wo, c = rem - r * Wo;
        int bi = img * Hi * Wi + (2 * r) * Wi + 2 * c;
        float v = 0.25f * (din[bi] + din[bi + 1] + din[bi + Wi] + din[bi + Wi + 1]);
        unsigned char a = mi[bi] | mi[bi + 1] | mi[bi + Wi] | mi[bi + Wi + 1];
        dout[i] = v;
        mo[i] = a;
    }
}

__global__ void k_final(float* out) {
    if (threadIdx.x == 0 && blockIdx.x == 0) {
        double ssi = 0;
        for (int i = 0; i < NIMG; i++) {
            double v = (double)g_cnt[i];
            if (v < 1.0) v = 1.0;
            ssi += g_rho[i] / v;
        }
        ssi /= (double)NIMG;
        double g = 0;
        for (int s = 0; s < 4; s++) {
            double cx = (double)g_cx[s]; if (cx < 1.0) cx = 1.0;
            double cy = (double)g_cy[s]; if (cy < 1.0) cy = 1.0;
            g += g_gx[s] / cx + g_gy[s] / cy;
        }
        out[0] = (float)(ssi + 0.5 * (g / 4.0));
    }
}

extern "C" void kernel_launch(void* const* d_in, const int* in_sizes, int n_in,
                              void* d_out, int out_size) {
    const float* pred = (const float*)d_in[0];
    const float* yv = (const float*)d_in[1];
    const void* mask = d_in[2];
    float* out = (float*)d_out;

    k_init<<<512, 256>>>(mask);
    dim3 gh(BPI, NIMG);
    k_hist<<<gh, 256>>>(pred, yv, mask);
    k_findbucket<<<128, 256>>>();
    k_collect<<<gh, 256>>>(pred, yv, mask);
    k_select<<<128, 256>>>();
    k_main<<<dim3(37, NIMG), 256>>>(pred, yv, mask);
    k_grad<<<2048, 256>>>(1);
    k_pool<<<1024, 256>>>(1);
    k_grad<<<1024, 256>>>(2);
    k_pool<<<512, 256>>>(2);
    k_grad<<<512, 256>>>(3);
    k_final<<<1, 32>>>(out);
}